// round 1
// baseline (speedup 1.0000x reference)
#include <cuda_runtime.h>
#include <math.h>

// ---------------------------------------------------------------------------
// StyleGAN2 block: up2 -> modconv3x3(demod)+noise+lrelu -> modconv3x3(demod)
//                  +noise+lrelu -> to_rgb (modconv1x1, no demod) + up2(rgb)
// Shapes: B=8, C=512, in 32x32, out 64x64. All fp32.
// Output layout: [rgb_out (8*3*64*64)] ++ [x (8*512*64*64)]
// ---------------------------------------------------------------------------

#define Bn 8
#define Cn 512
#define HIN 32
#define HOUT 64
#define PIX (HOUT*HOUT)          // 4096
#define XELEMS (Bn*Cn*PIX)       // 16,777,216
#define RGBELEMS (Bn*3*PIX)      // 98,304

// Scratch (allocation-free rule: __device__ globals)
__device__ float g_xA[XELEMS];   // upsampled+style-scaled input to conv0
__device__ float g_xB[XELEMS];   // conv0 output, scaled by s1 (input to conv1)
__device__ float g_s0[Bn*Cn], g_s1[Bn*Cn], g_s2[Bn*Cn];
__device__ float g_d0[Bn*Cn], g_d1[Bn*Cn];
__device__ float g_wsq0[Cn*Cn], g_wsq1[Cn*Cn];

// ---------------------------------------------------------------------------
// Styles: s = w @ sW^T + sB  for the three style projections
// ---------------------------------------------------------------------------
__global__ void k_styles(const float* __restrict__ w,
                         const float* __restrict__ sW0, const float* __restrict__ sB0,
                         const float* __restrict__ sW1, const float* __restrict__ sB1,
                         const float* __restrict__ sW2, const float* __restrict__ sB2)
{
    int idx = blockIdx.x * blockDim.x + threadIdx.x;
    if (idx >= 3 * Bn * Cn) return;
    int which = idx / (Bn * Cn);
    int rem   = idx % (Bn * Cn);
    int b = rem / Cn;
    int c = rem % Cn;
    const float* sW = (which == 0) ? sW0 : (which == 1) ? sW1 : sW2;
    const float* sB = (which == 0) ? sB0 : (which == 1) ? sB1 : sB2;
    const float* wr = w + b * Cn;
    const float* sr = sW + c * Cn;
    float acc = 0.f;
    #pragma unroll 8
    for (int k = 0; k < Cn; ++k) acc += wr[k] * sr[k];
    acc += sB[c];
    float* dst = (which == 0) ? g_s0 : (which == 1) ? g_s1 : g_s2;
    dst[b * Cn + c] = acc;
}

// ---------------------------------------------------------------------------
// wsq[o][i] = sum_k W[o][i][k]^2   (for both conv weights)
// ---------------------------------------------------------------------------
__global__ void k_wsq(const float* __restrict__ w0, const float* __restrict__ w1)
{
    int idx = blockIdx.x * blockDim.x + threadIdx.x;
    if (idx >= 2 * Cn * Cn) return;
    const float* W = (idx < Cn * Cn) ? w0 : w1;
    float* out     = (idx < Cn * Cn) ? g_wsq0 : g_wsq1;
    int e = idx & (Cn * Cn - 1);
    const float* p = W + (size_t)e * 9;
    float a = 0.f;
    #pragma unroll
    for (int t = 0; t < 9; ++t) a += p[t] * p[t];
    out[e] = a;
}

// ---------------------------------------------------------------------------
// d[b][o] = rsqrt( sum_i wsq[o][i] * s[b][i]^2 + eps )
// ---------------------------------------------------------------------------
__global__ void k_demod()
{
    int idx = blockIdx.x * blockDim.x + threadIdx.x;
    if (idx >= 2 * Bn * Cn) return;
    int which = idx / (Bn * Cn);
    int rem   = idx % (Bn * Cn);
    int b = rem / Cn;
    int o = rem % Cn;
    const float* wsq = which ? g_wsq1 : g_wsq0;
    const float* s   = which ? g_s1 : g_s0;
    const float* wr = wsq + o * Cn;
    const float* sr = s + b * Cn;
    float acc = 0.f;
    #pragma unroll 8
    for (int k = 0; k < Cn; ++k) { float sv = sr[k]; acc += wr[k] * sv * sv; }
    float d = rsqrtf(acc + 1e-8f);
    (which ? g_d1 : g_d0)[b * Cn + o] = d;
}

// ---------------------------------------------------------------------------
// Bilinear 2x upsample (half-pixel, matches torch align_corners=False and
// jax.image.resize for 2x) of maps, fused with style scale s0 -> g_xA
// ---------------------------------------------------------------------------
__global__ void k_up_maps(const float* __restrict__ maps)
{
    int idx = blockIdx.x * blockDim.x + threadIdx.x;
    if (idx >= XELEMS) return;
    int X  = idx & 63;
    int Y  = (idx >> 6) & 63;
    int bc = idx >> 12;                 // b*512 + c
    float s = g_s0[bc];

    int yl = (Y - 1) >> 1; int yu = yl + 1;
    float wyu = (Y & 1) ? 0.25f : 0.75f;
    yl = max(yl, 0); yu = min(yu, HIN - 1);
    int xl = (X - 1) >> 1; int xu = xl + 1;
    float wxu = (X & 1) ? 0.25f : 0.75f;
    xl = max(xl, 0); xu = min(xu, HIN - 1);

    const float* p = maps + (size_t)bc * (HIN * HIN);
    float v = (1.f - wyu) * ((1.f - wxu) * p[yl * HIN + xl] + wxu * p[yl * HIN + xu])
            +         wyu * ((1.f - wxu) * p[yu * HIN + xl] + wxu * p[yu * HIN + xu]);
    g_xA[idx] = v * s;
}

// ---------------------------------------------------------------------------
// 3x3 conv (shared weights across batch; input already style-scaled),
// implicit GEMM. Block: 64 out-channels x one 64-pixel row.
// Epilogue: *demod + bias + noise_scale*noise, leaky-relu(0.2),
//           optional per-(b,o) post-scale (next layer's style).
// ---------------------------------------------------------------------------
__global__ void __launch_bounds__(256) k_conv3x3(
    const float* __restrict__ in,    // [8][512][64][64]
    const float* __restrict__ W,     // [512][512][3][3]
    const float* __restrict__ dmod,  // [8][512]
    const float* __restrict__ bias,  // [512]
    const float* __restrict__ nsc,   // [512]
    const float* __restrict__ noise, // [8][1][64][64]
    const float* __restrict__ postScale, // [8][512] or nullptr
    float* __restrict__ out)         // [8][512][64][64]
{
    __shared__ __align__(16) float Wsm[72 * 64];     // [t=i*9+tap][o]  18 KB
    __shared__ __align__(16) float Ism[8 * 3 * 66];  // [i][r][x+1]     6.2 KB

    const int tid = threadIdx.x;
    const int tx = tid & 15;        // pixel group: x = tx*4 .. tx*4+3
    const int ty = tid >> 4;        // out-ch group: o = o0 + ty*4 .. +3
    const int y  = blockIdx.x;      // row 0..63
    const int o0 = blockIdx.y * 64; // out-channel tile
    const int b  = blockIdx.z;

    float acc[4][4] = {};

    const float* inB = in + (size_t)b * Cn * PIX;

    for (int ic0 = 0; ic0 < Cn; ic0 += 8) {
        // --- stage weights: W[o0+o][ic0*9 + t], t in [0,72) contiguous per o
        #pragma unroll
        for (int j = 0; j < 18; ++j) {
            int idx = j * 256 + tid;
            int o = idx / 72;
            int t = idx % 72;
            Wsm[t * 64 + o] = W[(size_t)(o0 + o) * 4608 + ic0 * 9 + t];
        }
        // --- stage input: 8 channels x 3 rows x (64 + 2 halo), zero-padded
        for (int idx = tid; idx < 8 * 3 * 66; idx += 256) {
            int i   = idx / 198;
            int rem = idx - i * 198;
            int r   = rem / 66;
            int xx  = rem - r * 66;
            int yy  = y - 1 + r;
            int gx  = xx - 1;
            float v = 0.f;
            if ((unsigned)yy < 64u && (unsigned)gx < 64u)
                v = inB[(size_t)(ic0 + i) * PIX + yy * 64 + gx];
            Ism[idx] = v;
        }
        __syncthreads();

        #pragma unroll
        for (int i = 0; i < 8; ++i) {
            #pragma unroll
            for (int ky = 0; ky < 3; ++ky) {
                float win[6];
                const float* ip = &Ism[(i * 3 + ky) * 66 + tx * 4];
                #pragma unroll
                for (int u = 0; u < 6; ++u) win[u] = ip[u];
                #pragma unroll
                for (int kx = 0; kx < 3; ++kx) {
                    float4 wv = *(const float4*)&Wsm[(i * 9 + ky * 3 + kx) * 64 + ty * 4];
                    #pragma unroll
                    for (int c = 0; c < 4; ++c) {
                        float iv = win[kx + c];
                        acc[0][c] += wv.x * iv;
                        acc[1][c] += wv.y * iv;
                        acc[2][c] += wv.z * iv;
                        acc[3][c] += wv.w * iv;
                    }
                }
            }
        }
        __syncthreads();
    }

    // --- epilogue
    float nz[4];
    {
        const float* np = noise + (size_t)b * PIX + y * 64 + tx * 4;
        #pragma unroll
        for (int c = 0; c < 4; ++c) nz[c] = np[c];
    }
    #pragma unroll
    for (int a = 0; a < 4; ++a) {
        int o = o0 + ty * 4 + a;
        float d   = dmod[b * Cn + o];
        float bi  = bias[o];
        float nsv = nsc[o];
        float ps  = postScale ? postScale[b * Cn + o] : 1.f;
        float v0 = acc[a][0] * d + bi + nsv * nz[0];
        float v1 = acc[a][1] * d + bi + nsv * nz[1];
        float v2 = acc[a][2] * d + bi + nsv * nz[2];
        float v3 = acc[a][3] * d + bi + nsv * nz[3];
        v0 = (v0 >= 0.f ? v0 : 0.2f * v0) * ps;
        v1 = (v1 >= 0.f ? v1 : 0.2f * v1) * ps;
        v2 = (v2 >= 0.f ? v2 : 0.2f * v2) * ps;
        v3 = (v3 >= 0.f ? v3 : 0.2f * v3) * ps;
        float4* op = (float4*)(out + ((size_t)(b * Cn + o) * 64 + y) * 64 + tx * 4);
        *op = make_float4(v0, v1, v2, v3);
    }
}

// ---------------------------------------------------------------------------
// to_rgb: rgb_out = up2(rgb) + rgbB + sum_c (rgbW[r][c]*s2[b][c]) * x[b][c]
// Block handles (b, 4 rows); 256 threads = 4 rows x 64 cols.
// ---------------------------------------------------------------------------
__global__ void __launch_bounds__(256) k_rgb(
    const float* __restrict__ x,     // [8][512][64][64]  (the x output)
    const float* __restrict__ rgb,   // [8][3][32][32]
    const float* __restrict__ rgbW,  // [3][512]
    const float* __restrict__ rgbB,  // [3]
    float* __restrict__ outRGB)      // [8][3][64][64]
{
    __shared__ float ws[3 * Cn];
    int b    = blockIdx.x >> 4;
    int yblk = blockIdx.x & 15;
    int tid  = threadIdx.x;

    for (int idx = tid; idx < 3 * Cn; idx += 256)
        ws[idx] = rgbW[idx] * g_s2[b * Cn + (idx & (Cn - 1))];
    __syncthreads();

    int dy = tid >> 6;
    int X  = tid & 63;
    int Y  = yblk * 4 + dy;

    const float* xp = x + (size_t)b * Cn * PIX + Y * 64 + X;
    float a0 = 0.f, a1 = 0.f, a2 = 0.f;
    #pragma unroll 8
    for (int c = 0; c < Cn; ++c) {
        float v = xp[(size_t)c * PIX];
        a0 += ws[c] * v;
        a1 += ws[Cn + c] * v;
        a2 += ws[2 * Cn + c] * v;
    }

    int yl = (Y - 1) >> 1; int yu = yl + 1;
    float wyu = (Y & 1) ? 0.25f : 0.75f;
    yl = max(yl, 0); yu = min(yu, HIN - 1);
    int xl = (X - 1) >> 1; int xu = xl + 1;
    float wxu = (X & 1) ? 0.25f : 0.75f;
    xl = max(xl, 0); xu = min(xu, HIN - 1);

    float accs[3] = {a0, a1, a2};
    #pragma unroll
    for (int r = 0; r < 3; ++r) {
        const float* p = rgb + (size_t)(b * 3 + r) * (HIN * HIN);
        float up = (1.f - wyu) * ((1.f - wxu) * p[yl * HIN + xl] + wxu * p[yl * HIN + xu])
                 +         wyu * ((1.f - wxu) * p[yu * HIN + xl] + wxu * p[yu * HIN + xu]);
        outRGB[((size_t)(b * 3 + r) * 64 + Y) * 64 + X] = up + accs[r] + rgbB[r];
    }
}

// ---------------------------------------------------------------------------
extern "C" void kernel_launch(void* const* d_in, const int* in_sizes, int n_in,
                              void* d_out, int out_size)
{
    const float* maps   = (const float*)d_in[0];
    const float* w      = (const float*)d_in[1];
    const float* rgb    = (const float*)d_in[2];
    const float* noise0 = (const float*)d_in[3];
    const float* noise1 = (const float*)d_in[4];
    const float* w0     = (const float*)d_in[5];
    const float* b0     = (const float*)d_in[6];
    const float* sW0    = (const float*)d_in[7];
    const float* sB0    = (const float*)d_in[8];
    const float* ns0    = (const float*)d_in[9];
    const float* w1     = (const float*)d_in[10];
    const float* b1     = (const float*)d_in[11];
    const float* sW1    = (const float*)d_in[12];
    const float* sB1    = (const float*)d_in[13];
    const float* ns1    = (const float*)d_in[14];
    const float* rgbW   = (const float*)d_in[15];
    const float* rgbB   = (const float*)d_in[16];
    const float* rgbSW  = (const float*)d_in[17];
    const float* rgbSB  = (const float*)d_in[18];

    float* out    = (float*)d_out;
    float* outRGB = out;
    float* outX   = out + RGBELEMS;

    float *xA, *xB, *d0p, *d1p, *s1p;
    cudaGetSymbolAddress((void**)&xA,  g_xA);
    cudaGetSymbolAddress((void**)&xB,  g_xB);
    cudaGetSymbolAddress((void**)&d0p, g_d0);
    cudaGetSymbolAddress((void**)&d1p, g_d1);
    cudaGetSymbolAddress((void**)&s1p, g_s1);

    k_styles<<<(3 * Bn * Cn + 255) / 256, 256>>>(w, sW0, sB0, sW1, sB1, rgbSW, rgbSB);
    k_wsq<<<(2 * Cn * Cn + 255) / 256, 256>>>(w0, w1);
    k_demod<<<(2 * Bn * Cn + 255) / 256, 256>>>();
    k_up_maps<<<XELEMS / 256, 256>>>(maps);

    dim3 gconv(64, Cn / 64, Bn);
    k_conv3x3<<<gconv, 256>>>(xA, w0, d0p, b0, ns0, noise0, s1p, xB);
    k_conv3x3<<<gconv, 256>>>(xB, w1, d1p, b1, ns1, noise1, nullptr, outX);

    k_rgb<<<Bn * 16, 256>>>(outX, rgb, rgbW, rgbB, outRGB);
}

// round 3
// speedup vs baseline: 4.5289x; 4.5289x over previous
#include <cuda_runtime.h>
#include <cuda_bf16.h>
#include <cstdint>
#include <math.h>

// ===========================================================================
// StyleGAN2 block, convs via warp-level mma.sync (bf16 hi+lo split, 3 MMAs).
// Plain sm_103 PTX target compatible (no tcgen05 / no TMA).
// Output: [rgb_out (8*3*64*64)] ++ [x (8*512*64*64)], fp32.
// ===========================================================================

#define Bn 8
#define Cn 512
#define HIN 32
#define PIX 4096                 // 64*64
#define XELEMS (Bn*Cn*PIX)
#define RGBELEMS (Bn*3*PIX)
#define PADHW 66                 // 64 + 2 halo
#define PADCELLS (PADHW*PADHW)   // 4356

// ---------------- device scratch (allocation-free rule) -------------------
__device__ uint32_t g_xa[(size_t)Bn*PADCELLS*Cn];   // padded HWC (hi,lo) pairs
__device__ uint32_t g_xb[(size_t)Bn*PADCELLS*Cn];
__device__ uint32_t g_wt0[9*Cn*Cn];                 // [tap][oc][ic] (hi,lo) pairs
__device__ uint32_t g_wt1[9*Cn*Cn];
__device__ float g_s0[Bn*Cn], g_s1[Bn*Cn], g_s2[Bn*Cn];
__device__ float g_d0[Bn*Cn], g_d1[Bn*Cn];
__device__ float g_wsq0[Cn*Cn], g_wsq1[Cn*Cn];

// ---------------- helpers --------------------------------------------------
__device__ __forceinline__ uint32_t smem_u32(const void* p) {
    uint32_t a;
    asm("{ .reg .u64 t; cvta.to.shared.u64 t, %1; cvt.u32.u64 %0, t; }"
        : "=r"(a) : "l"(p));
    return a;
}

__device__ __forceinline__ void ldsm_x4(uint32_t* r, uint32_t addr) {
    asm volatile("ldmatrix.sync.aligned.m8n8.x4.shared.b16 {%0,%1,%2,%3}, [%4];"
        : "=r"(r[0]), "=r"(r[1]), "=r"(r[2]), "=r"(r[3]) : "r"(addr));
}
__device__ __forceinline__ void ldsm_x2(uint32_t* r, uint32_t addr) {
    asm volatile("ldmatrix.sync.aligned.m8n8.x2.shared.b16 {%0,%1}, [%2];"
        : "=r"(r[0]), "=r"(r[1]) : "r"(addr));
}
__device__ __forceinline__ void mma_bf16(float* c, const uint32_t* a,
                                         const uint32_t* b) {
    asm volatile(
        "mma.sync.aligned.m16n8k16.row.col.f32.bf16.bf16.f32 "
        "{%0,%1,%2,%3},{%4,%5,%6,%7},{%8,%9},{%0,%1,%2,%3};"
        : "+f"(c[0]), "+f"(c[1]), "+f"(c[2]), "+f"(c[3])
        : "r"(a[0]), "r"(a[1]), "r"(a[2]), "r"(a[3]), "r"(b[0]), "r"(b[1]));
}

// ---------------------------------------------------------------------------
// styles
// ---------------------------------------------------------------------------
__global__ void k_styles(const float* __restrict__ w,
                         const float* __restrict__ sW0, const float* __restrict__ sB0,
                         const float* __restrict__ sW1, const float* __restrict__ sB1,
                         const float* __restrict__ sW2, const float* __restrict__ sB2)
{
    int idx = blockIdx.x * blockDim.x + threadIdx.x;
    if (idx >= 3 * Bn * Cn) return;
    int which = idx / (Bn * Cn);
    int rem   = idx % (Bn * Cn);
    int b = rem / Cn, c = rem % Cn;
    const float* sW = (which == 0) ? sW0 : (which == 1) ? sW1 : sW2;
    const float* sB = (which == 0) ? sB0 : (which == 1) ? sB1 : sB2;
    const float* wr = w + b * Cn;
    const float* sr = sW + c * Cn;
    float acc = 0.f;
    #pragma unroll 8
    for (int k = 0; k < Cn; ++k) acc += wr[k] * sr[k];
    acc += sB[c];
    ((which == 0) ? g_s0 : (which == 1) ? g_s1 : g_s2)[b * Cn + c] = acc;
}

__global__ void k_wsq(const float* __restrict__ w0, const float* __restrict__ w1)
{
    int idx = blockIdx.x * blockDim.x + threadIdx.x;
    if (idx >= 2 * Cn * Cn) return;
    const float* W = (idx < Cn * Cn) ? w0 : w1;
    float* out     = (idx < Cn * Cn) ? g_wsq0 : g_wsq1;
    int e = idx & (Cn * Cn - 1);
    const float* p = W + (size_t)e * 9;
    float a = 0.f;
    #pragma unroll
    for (int t = 0; t < 9; ++t) a += p[t] * p[t];
    out[e] = a;
}

__global__ void k_demod()
{
    int idx = blockIdx.x * blockDim.x + threadIdx.x;
    if (idx >= 2 * Bn * Cn) return;
    int which = idx / (Bn * Cn);
    int rem   = idx % (Bn * Cn);
    int b = rem / Cn, o = rem % Cn;
    const float* wsq = which ? g_wsq1 : g_wsq0;
    const float* s   = which ? g_s1 : g_s0;
    const float* wr = wsq + o * Cn;
    const float* sr = s + b * Cn;
    float acc = 0.f;
    #pragma unroll 8
    for (int k = 0; k < Cn; ++k) { float sv = sr[k]; acc += wr[k] * sv * sv; }
    (which ? g_d1 : g_d0)[b * Cn + o] = rsqrtf(acc + 1e-8f);
}

// ---------------------------------------------------------------------------
// weight prep: W[o][i][tap] fp32 -> g_wt[tap][o][i] (hi,lo) bf16 pairs
// ---------------------------------------------------------------------------
__global__ void k_wprep(const float* __restrict__ w0, const float* __restrict__ w1)
{
    int idx = blockIdx.x * blockDim.x + threadIdx.x;
    if (idx >= 2 * 9 * Cn * Cn) return;
    int layer = idx / (9 * Cn * Cn);
    int r = idx % (9 * Cn * Cn);
    int tap = r / (Cn * Cn);
    int rr = r % (Cn * Cn);
    int o = rr >> 9, i = rr & 511;
    const float* W = layer ? w1 : w0;
    float v = W[((size_t)o * Cn + i) * 9 + tap];
    __nv_bfloat16 h = __float2bfloat16(v);
    __nv_bfloat16 l = __float2bfloat16(v - __bfloat162float(h));
    uint32_t pk = ((uint32_t)__bfloat16_as_ushort(l) << 16) | (uint32_t)__bfloat16_as_ushort(h);
    (layer ? g_wt1 : g_wt0)[((size_t)tap * Cn + o) * Cn + i] = pk;
}

// ---------------------------------------------------------------------------
// zero the halo borders of g_xa / g_xb
// ---------------------------------------------------------------------------
__global__ void k_zero()
{
    int idx = blockIdx.x * blockDim.x + threadIdx.x;
    if (idx >= Bn * 260 * Cn) return;
    int c = idx & 511;
    int cell = (idx >> 9) % 260;
    int b = (idx >> 9) / 260;
    int y, x;
    if (cell < 66)       { y = 0;  x = cell; }
    else if (cell < 132) { y = 65; x = cell - 66; }
    else { int r = cell - 132; y = 1 + (r & 63); x = (r >> 6) ? 65 : 0; }
    size_t a = (((size_t)b * PADHW + y) * PADHW + x) * Cn + c;
    g_xa[a] = 0u;
    g_xb[a] = 0u;
}

// ---------------------------------------------------------------------------
// upsample maps 2x bilinear, *s0, write padded HWC (hi,lo) pairs to g_xa
// ---------------------------------------------------------------------------
__global__ void __launch_bounds__(256) k_up(const float* __restrict__ maps)
{
    __shared__ uint32_t tile[64 * 65];
    int bx = blockIdx.x;
    int b = bx >> 6, y = bx & 63;
    int tid = threadIdx.x;

    int yl = (y - 1) >> 1, yu = yl + 1;
    float wyu = (y & 1) ? 0.25f : 0.75f;
    yl = max(yl, 0); yu = min(yu, HIN - 1);

    for (int c0 = 0; c0 < Cn; c0 += 64) {
        #pragma unroll
        for (int k = 0; k < 16; ++k) {
            int e = tid + (k << 8);
            int c = e >> 6, x = e & 63;
            int xl = (x - 1) >> 1, xu = xl + 1;
            float wxu = (x & 1) ? 0.25f : 0.75f;
            xl = max(xl, 0); xu = min(xu, HIN - 1);
            const float* p = maps + (size_t)(b * Cn + c0 + c) * (HIN * HIN);
            float v = (1.f - wyu) * ((1.f - wxu) * p[yl*HIN+xl] + wxu * p[yl*HIN+xu])
                    +         wyu * ((1.f - wxu) * p[yu*HIN+xl] + wxu * p[yu*HIN+xu]);
            v *= g_s0[b * Cn + c0 + c];
            __nv_bfloat16 h = __float2bfloat16(v);
            __nv_bfloat16 l = __float2bfloat16(v - __bfloat162float(h));
            tile[c * 65 + x] = ((uint32_t)__bfloat16_as_ushort(l) << 16) |
                               (uint32_t)__bfloat16_as_ushort(h);
        }
        __syncthreads();
        #pragma unroll
        for (int k = 0; k < 16; ++k) {
            int e = tid + (k << 8);
            int x = e >> 6, c = e & 63;
            g_xa[(((size_t)b * PADHW + y + 1) * PADHW + x + 1) * Cn + c0 + c] = tile[c * 65 + x];
        }
        __syncthreads();
    }
}

// ---------------------------------------------------------------------------
// staging: one K-chunk (tap, 64 ic) -> smem AH/AL (128oc x 64ic) and
// BH/BL (128px x 64ic) bf16 tiles, XOR-swizzled rows of 128B. 512 threads.
// ---------------------------------------------------------------------------
__device__ __forceinline__ void stage_chunk(
    char* dbase, int s,
    const uint32_t* __restrict__ xin, const uint32_t* __restrict__ wt,
    int o0, int b, int y0, int chunk, int tid)
{
    const int tap = chunk >> 3;
    const int ic0 = (chunk & 7) << 6;
    const int ky = tap / 3;
    const int kx = tap - ky * 3;
    char* AH = dbase + s * 65536;
    char* AL = AH + 16384;
    char* BH = AH + 32768;
    char* BL = AH + 49152;
    #pragma unroll
    for (int k = 0; k < 4; ++k) {
        int t = tid + (k << 9);
        if (t < 1024) {
            int o = t >> 3, g = t & 7;
            const uint4* src = (const uint4*)(wt + (((size_t)tap * Cn + o0 + o) * Cn + ic0 + g * 8));
            uint4 w0 = src[0], w1 = src[1];
            uint32_t off = (uint32_t)((o << 7) + (g << 4));
            off ^= (off >> 3) & 0x70;
            *(uint4*)(AH + off) = make_uint4(
                __byte_perm(w0.x, w0.y, 0x5410), __byte_perm(w0.z, w0.w, 0x5410),
                __byte_perm(w1.x, w1.y, 0x5410), __byte_perm(w1.z, w1.w, 0x5410));
            *(uint4*)(AL + off) = make_uint4(
                __byte_perm(w0.x, w0.y, 0x7632), __byte_perm(w0.z, w0.w, 0x7632),
                __byte_perm(w1.x, w1.y, 0x7632), __byte_perm(w1.z, w1.w, 0x7632));
        } else {
            int p = (t - 1024) >> 3, g = t & 7;
            int dy = p >> 6, x = p & 63;
            const uint4* src = (const uint4*)(xin +
                ((((size_t)b * PADHW + y0 + dy + ky) * PADHW) + x + kx) * Cn + ic0 + g * 8);
            uint4 w0 = src[0], w1 = src[1];
            uint32_t off = (uint32_t)((p << 7) + (g << 4));
            off ^= (off >> 3) & 0x70;
            *(uint4*)(BH + off) = make_uint4(
                __byte_perm(w0.x, w0.y, 0x5410), __byte_perm(w0.z, w0.w, 0x5410),
                __byte_perm(w1.x, w1.y, 0x5410), __byte_perm(w1.z, w1.w, 0x5410));
            *(uint4*)(BL + off) = make_uint4(
                __byte_perm(w0.x, w0.y, 0x7632), __byte_perm(w0.z, w0.w, 0x7632),
                __byte_perm(w1.x, w1.y, 0x7632), __byte_perm(w1.z, w1.w, 0x7632));
        }
    }
}

// ---------------------------------------------------------------------------
// conv via mma.sync: D[128 oc, 128 px] over 72 chunks, 3 MMAs per K=16 step.
// 512 threads, 16 warps in a 4(m) x 4(n) grid, warp tile 32oc x 32px.
// EPI=0: -> (hi,lo) pairs into padded HWC buffer (pre-scaled by next style)
// EPI=1: -> fp32 NCHW into d_out x region
// ---------------------------------------------------------------------------
template<int EPI>
__global__ void __launch_bounds__(512) k_conv(
    const uint32_t* __restrict__ xin,
    const uint32_t* __restrict__ wt,
    const float* __restrict__ dmod,
    const float* __restrict__ bias,
    const float* __restrict__ nsc,
    const float* __restrict__ noise,
    const float* __restrict__ post,
    uint32_t* __restrict__ outPairs,
    float* __restrict__ outF)
{
    extern __shared__ __align__(16) char dsm_raw[];
    char* dbase = (char*)(((uintptr_t)dsm_raw + 1023) & ~(uintptr_t)1023);
    const uint32_t sb = smem_u32(dbase);
    const int tid = threadIdx.x;
    const int lane = tid & 31, wid = tid >> 5;
    const int mw = wid >> 2, nw = wid & 3;
    const int nt = blockIdx.x;
    const int o0 = blockIdx.y * 128;
    const int b  = nt >> 5;
    const int y0 = (nt & 31) * 2;

    float acc[2][4][4] = {};

    const int a_row = lane & 15;
    const int a_c16 = (lane >> 4) << 4;
    const int b_row = lane & 7;
    const int b_c16 = ((lane >> 3) & 1) << 4;

    stage_chunk(dbase, 0, xin, wt, o0, b, y0, 0, tid);
    __syncthreads();

    int cur = 0;
    for (int c = 0; c < 72; ++c) {
        if (c + 1 < 72) stage_chunk(dbase, cur ^ 1, xin, wt, o0, b, y0, c + 1, tid);

        const uint32_t AHb = sb + cur * 65536;
        const uint32_t ALb = AHb + 16384;
        const uint32_t BHb = AHb + 32768;
        const uint32_t BLb = AHb + 49152;

        #pragma unroll
        for (int ks = 0; ks < 4; ++ks) {
            uint32_t ah[2][4], al[2][4], bh[4][2], bl[4][2];
            #pragma unroll
            for (int sm = 0; sm < 2; ++sm) {
                uint32_t off = (uint32_t)((mw * 32 + sm * 16 + a_row) * 128 + ks * 32 + a_c16);
                off ^= (off >> 3) & 0x70;
                ldsm_x4(ah[sm], AHb + off);
                ldsm_x4(al[sm], ALb + off);
            }
            #pragma unroll
            for (int sn = 0; sn < 4; ++sn) {
                uint32_t off = (uint32_t)((nw * 32 + sn * 8 + b_row) * 128 + ks * 32 + b_c16);
                off ^= (off >> 3) & 0x70;
                ldsm_x2(bh[sn], BHb + off);
                ldsm_x2(bl[sn], BLb + off);
            }
            #pragma unroll
            for (int sm = 0; sm < 2; ++sm)
                #pragma unroll
                for (int sn = 0; sn < 4; ++sn) {
                    mma_bf16(acc[sm][sn], ah[sm], bh[sn]);
                    mma_bf16(acc[sm][sn], ah[sm], bl[sn]);
                    mma_bf16(acc[sm][sn], al[sm], bh[sn]);
                }
        }
        __syncthreads();
        cur ^= 1;
    }

    // ---- epilogue. c-frag layout: e0,e1=(row, col/col+1) e2,e3=(row+8, ..)
    const int groupM = lane >> 2;
    const int groupN = 2 * (lane & 3);
    const float* np = noise + (size_t)b * PIX + y0 * 64;

    if (EPI == 0) {
        uint32_t* tp = (uint32_t*)dbase;   // [128 px][132] u32 (hi,lo) pairs
        #pragma unroll
        for (int sm = 0; sm < 2; ++sm) {
            #pragma unroll
            for (int ro = 0; ro < 2; ++ro) {
                int ocl = mw * 32 + sm * 16 + groupM + ro * 8;
                int oc = o0 + ocl;
                float d  = dmod[b * Cn + oc];
                float bi = bias[oc];
                float nv = nsc[oc];
                float ps = post[b * Cn + oc];
                #pragma unroll
                for (int sn = 0; sn < 4; ++sn) {
                    int px = nw * 32 + sn * 8 + groupN;
                    #pragma unroll
                    for (int e = 0; e < 2; ++e) {
                        float v = acc[sm][sn][ro * 2 + e] * d + bi + nv * np[px + e];
                        v = (v >= 0.f) ? v : 0.2f * v;
                        v *= ps;
                        __nv_bfloat16 h = __float2bfloat16(v);
                        __nv_bfloat16 l = __float2bfloat16(v - __bfloat162float(h));
                        tp[(px + e) * 132 + ocl] =
                            ((uint32_t)__bfloat16_as_ushort(l) << 16) |
                            (uint32_t)__bfloat16_as_ushort(h);
                    }
                }
            }
        }
        __syncthreads();
        int p = tid >> 2, q = tid & 3;
        int yy = y0 + (p >> 6), xx = p & 63;
        uint4* dst = (uint4*)(outPairs +
            (((size_t)b * PADHW + yy + 1) * PADHW + xx + 1) * Cn + o0 + q * 32);
        const uint4* src = (const uint4*)(tp + p * 132 + q * 32);
        #pragma unroll
        for (int i = 0; i < 8; ++i) dst[i] = src[i];
    } else {
        #pragma unroll
        for (int sm = 0; sm < 2; ++sm) {
            #pragma unroll
            for (int ro = 0; ro < 2; ++ro) {
                int ocl = mw * 32 + sm * 16 + groupM + ro * 8;
                int oc = o0 + ocl;
                float d  = dmod[b * Cn + oc];
                float bi = bias[oc];
                float nv = nsc[oc];
                #pragma unroll
                for (int sn = 0; sn < 4; ++sn) {
                    int px = nw * 32 + sn * 8 + groupN;
                    float v0 = acc[sm][sn][ro * 2 + 0] * d + bi + nv * np[px + 0];
                    float v1 = acc[sm][sn][ro * 2 + 1] * d + bi + nv * np[px + 1];
                    v0 = (v0 >= 0.f) ? v0 : 0.2f * v0;
                    v1 = (v1 >= 0.f) ? v1 : 0.2f * v1;
                    int y = y0 + (px >> 6), x = px & 63;
                    float2* dp = (float2*)(outF + ((size_t)(b * Cn + oc) * 64 + y) * 64 + x);
                    *dp = make_float2(v0, v1);
                }
            }
        }
    }
}

// ---------------------------------------------------------------------------
// to_rgb: rgb_out = up2(rgb) + rgbB + (rgbW*s2) . x
// ---------------------------------------------------------------------------
__global__ void __launch_bounds__(256) k_rgb(
    const float* __restrict__ x,
    const float* __restrict__ rgb,
    const float* __restrict__ rgbW,
    const float* __restrict__ rgbB,
    float* __restrict__ outRGB)
{
    __shared__ float ws[3 * Cn];
    int b    = blockIdx.x >> 4;
    int yblk = blockIdx.x & 15;
    int tid  = threadIdx.x;

    for (int idx = tid; idx < 3 * Cn; idx += 256)
        ws[idx] = rgbW[idx] * g_s2[b * Cn + (idx & (Cn - 1))];
    __syncthreads();

    int dy = tid >> 6;
    int X  = tid & 63;
    int Y  = yblk * 4 + dy;

    const float* xp = x + (size_t)b * Cn * PIX + Y * 64 + X;
    float a0 = 0.f, a1 = 0.f, a2 = 0.f;
    #pragma unroll 8
    for (int c = 0; c < Cn; ++c) {
        float v = xp[(size_t)c * PIX];
        a0 += ws[c] * v;
        a1 += ws[Cn + c] * v;
        a2 += ws[2 * Cn + c] * v;
    }

    int yl = (Y - 1) >> 1; int yu = yl + 1;
    float wyu = (Y & 1) ? 0.25f : 0.75f;
    yl = max(yl, 0); yu = min(yu, HIN - 1);
    int xl = (X - 1) >> 1; int xu = xl + 1;
    float wxu = (X & 1) ? 0.25f : 0.75f;
    xl = max(xl, 0); xu = min(xu, HIN - 1);

    float accs[3] = {a0, a1, a2};
    #pragma unroll
    for (int r = 0; r < 3; ++r) {
        const float* p = rgb + (size_t)(b * 3 + r) * (HIN * HIN);
        float up = (1.f - wyu) * ((1.f - wxu) * p[yl*HIN+xl] + wxu * p[yl*HIN+xu])
                 +         wyu * ((1.f - wxu) * p[yu*HIN+xl] + wxu * p[yu*HIN+xu]);
        outRGB[((size_t)(b * 3 + r) * 64 + Y) * 64 + X] = up + accs[r] + rgbB[r];
    }
}

// ---------------------------------------------------------------------------
extern "C" void kernel_launch(void* const* d_in, const int* in_sizes, int n_in,
                              void* d_out, int out_size)
{
    const float* maps   = (const float*)d_in[0];
    const float* w      = (const float*)d_in[1];
    const float* rgb    = (const float*)d_in[2];
    const float* noise0 = (const float*)d_in[3];
    const float* noise1 = (const float*)d_in[4];
    const float* w0     = (const float*)d_in[5];
    const float* b0     = (const float*)d_in[6];
    const float* sW0    = (const float*)d_in[7];
    const float* sB0    = (const float*)d_in[8];
    const float* ns0    = (const float*)d_in[9];
    const float* w1     = (const float*)d_in[10];
    const float* b1     = (const float*)d_in[11];
    const float* sW1    = (const float*)d_in[12];
    const float* sB1    = (const float*)d_in[13];
    const float* ns1    = (const float*)d_in[14];
    const float* rgbW   = (const float*)d_in[15];
    const float* rgbB   = (const float*)d_in[16];
    const float* rgbSW  = (const float*)d_in[17];
    const float* rgbSB  = (const float*)d_in[18];

    float* out    = (float*)d_out;
    float* outRGB = out;
    float* outX   = out + RGBELEMS;

    uint32_t *xa, *xb, *wt0, *wt1;
    float *d0p, *d1p, *s1p;
    cudaGetSymbolAddress((void**)&xa,  g_xa);
    cudaGetSymbolAddress((void**)&xb,  g_xb);
    cudaGetSymbolAddress((void**)&wt0, g_wt0);
    cudaGetSymbolAddress((void**)&wt1, g_wt1);
    cudaGetSymbolAddress((void**)&d0p, g_d0);
    cudaGetSymbolAddress((void**)&d1p, g_d1);
    cudaGetSymbolAddress((void**)&s1p, g_s1);

    const int DSM = 1024 + 2 * 65536;
    cudaFuncSetAttribute(k_conv<0>, cudaFuncAttributeMaxDynamicSharedMemorySize, DSM);
    cudaFuncSetAttribute(k_conv<1>, cudaFuncAttributeMaxDynamicSharedMemorySize, DSM);

    k_styles<<<(3 * Bn * Cn + 255) / 256, 256>>>(w, sW0, sB0, sW1, sB1, rgbSW, rgbSB);
    k_wsq<<<(2 * Cn * Cn + 255) / 256, 256>>>(w0, w1);
    k_demod<<<(2 * Bn * Cn + 255) / 256, 256>>>();
    k_wprep<<<(2 * 9 * Cn * Cn + 255) / 256, 256>>>(w0, w1);
    k_zero<<<(Bn * 260 * Cn + 255) / 256, 256>>>();
    k_up<<<Bn * 64, 256>>>(maps);

    dim3 gconv(256, 4);
    k_conv<0><<<gconv, 512, DSM>>>(xa, wt0, d0p, b0, ns0, noise0, s1p, xb, nullptr);
    k_conv<1><<<gconv, 512, DSM>>>(xb, wt1, d1p, b1, ns1, noise1, nullptr, nullptr, outX);

    k_rgb<<<Bn * 16, 256>>>(outX, rgb, rgbW, rgbB, outRGB);
}

// round 4
// speedup vs baseline: 5.9951x; 1.3237x over previous
#include <cuda_runtime.h>
#include <cuda_bf16.h>
#include <cstdint>
#include <math.h>

// ===========================================================================
// StyleGAN2 block, convs via warp-level mma.sync (bf16 hi+lo split, 3 MMAs),
// cp.async 3-stage pipeline, separate hi/lo global planes.
// Output: [rgb_out (8*3*64*64)] ++ [x (8*512*64*64)], fp32.
// ===========================================================================

#define Bn 8
#define Cn 512
#define HIN 32
#define PIX 4096                 // 64*64
#define XELEMS (Bn*Cn*PIX)
#define RGBELEMS (Bn*3*PIX)
#define PADHW 66                 // 64 + 2 halo
#define PADCELLS (PADHW*PADHW)   // 4356

// ---------------- device scratch (allocation-free rule) -------------------
__device__ __nv_bfloat16 g_xaH[(size_t)Bn*PADCELLS*Cn];
__device__ __nv_bfloat16 g_xaL[(size_t)Bn*PADCELLS*Cn];
__device__ __nv_bfloat16 g_xbH[(size_t)Bn*PADCELLS*Cn];
__device__ __nv_bfloat16 g_xbL[(size_t)Bn*PADCELLS*Cn];
__device__ __nv_bfloat16 g_wt0H[9*Cn*Cn], g_wt0L[9*Cn*Cn];
__device__ __nv_bfloat16 g_wt1H[9*Cn*Cn], g_wt1L[9*Cn*Cn];
__device__ float g_s0[Bn*Cn], g_s1[Bn*Cn], g_s2[Bn*Cn];
__device__ float g_d0[Bn*Cn], g_d1[Bn*Cn];
__device__ float g_wsq0[Cn*Cn], g_wsq1[Cn*Cn];

// ---------------- helpers --------------------------------------------------
__device__ __forceinline__ uint32_t smem_u32(const void* p) {
    uint32_t a;
    asm("{ .reg .u64 t; cvta.to.shared.u64 t, %1; cvt.u32.u64 %0, t; }"
        : "=r"(a) : "l"(p));
    return a;
}
__device__ __forceinline__ void ldsm_x4(uint32_t* r, uint32_t addr) {
    asm volatile("ldmatrix.sync.aligned.m8n8.x4.shared.b16 {%0,%1,%2,%3}, [%4];"
        : "=r"(r[0]), "=r"(r[1]), "=r"(r[2]), "=r"(r[3]) : "r"(addr));
}
__device__ __forceinline__ void ldsm_x2(uint32_t* r, uint32_t addr) {
    asm volatile("ldmatrix.sync.aligned.m8n8.x2.shared.b16 {%0,%1}, [%2];"
        : "=r"(r[0]), "=r"(r[1]) : "r"(addr));
}
__device__ __forceinline__ void mma_bf16(float* c, const uint32_t* a,
                                         const uint32_t* b) {
    asm volatile(
        "mma.sync.aligned.m16n8k16.row.col.f32.bf16.bf16.f32 "
        "{%0,%1,%2,%3},{%4,%5,%6,%7},{%8,%9},{%0,%1,%2,%3};"
        : "+f"(c[0]), "+f"(c[1]), "+f"(c[2]), "+f"(c[3])
        : "r"(a[0]), "r"(a[1]), "r"(a[2]), "r"(a[3]), "r"(b[0]), "r"(b[1]));
}
__device__ __forceinline__ void cp16(uint32_t dst, const void* src) {
    asm volatile("cp.async.cg.shared.global [%0], [%1], 16;"
        :: "r"(dst), "l"(src));
}
#define CP_COMMIT() asm volatile("cp.async.commit_group;" ::: "memory")
#define CP_WAIT1()  asm volatile("cp.async.wait_group 1;" ::: "memory")

// ---------------------------------------------------------------------------
// styles
// ---------------------------------------------------------------------------
__global__ void k_styles(const float* __restrict__ w,
                         const float* __restrict__ sW0, const float* __restrict__ sB0,
                         const float* __restrict__ sW1, const float* __restrict__ sB1,
                         const float* __restrict__ sW2, const float* __restrict__ sB2)
{
    int idx = blockIdx.x * blockDim.x + threadIdx.x;
    if (idx >= 3 * Bn * Cn) return;
    int which = idx / (Bn * Cn);
    int rem   = idx % (Bn * Cn);
    int b = rem / Cn, c = rem % Cn;
    const float* sW = (which == 0) ? sW0 : (which == 1) ? sW1 : sW2;
    const float* sB = (which == 0) ? sB0 : (which == 1) ? sB1 : sB2;
    const float* wr = w + b * Cn;
    const float* sr = sW + c * Cn;
    float acc = 0.f;
    #pragma unroll 8
    for (int k = 0; k < Cn; ++k) acc += wr[k] * sr[k];
    acc += sB[c];
    ((which == 0) ? g_s0 : (which == 1) ? g_s1 : g_s2)[b * Cn + c] = acc;
}

__global__ void k_wsq(const float* __restrict__ w0, const float* __restrict__ w1)
{
    int idx = blockIdx.x * blockDim.x + threadIdx.x;
    if (idx >= 2 * Cn * Cn) return;
    const float* W = (idx < Cn * Cn) ? w0 : w1;
    float* out     = (idx < Cn * Cn) ? g_wsq0 : g_wsq1;
    int e = idx & (Cn * Cn - 1);
    const float* p = W + (size_t)e * 9;
    float a = 0.f;
    #pragma unroll
    for (int t = 0; t < 9; ++t) a += p[t] * p[t];
    out[e] = a;
}

__global__ void k_demod()
{
    int idx = blockIdx.x * blockDim.x + threadIdx.x;
    if (idx >= 2 * Bn * Cn) return;
    int which = idx / (Bn * Cn);
    int rem   = idx % (Bn * Cn);
    int b = rem / Cn, o = rem % Cn;
    const float* wsq = which ? g_wsq1 : g_wsq0;
    const float* s   = which ? g_s1 : g_s0;
    const float* wr = wsq + o * Cn;
    const float* sr = s + b * Cn;
    float acc = 0.f;
    #pragma unroll 8
    for (int k = 0; k < Cn; ++k) { float sv = sr[k]; acc += wr[k] * sv * sv; }
    (which ? g_d1 : g_d0)[b * Cn + o] = rsqrtf(acc + 1e-8f);
}

// ---------------------------------------------------------------------------
// weight prep: W[o][i][tap] fp32 -> hi/lo bf16 planes [tap][oc][ic]
// ---------------------------------------------------------------------------
__global__ void k_wprep(const float* __restrict__ w0, const float* __restrict__ w1)
{
    int idx = blockIdx.x * blockDim.x + threadIdx.x;
    if (idx >= 2 * 9 * Cn * Cn) return;
    int layer = idx / (9 * Cn * Cn);
    int r = idx % (9 * Cn * Cn);
    int tap = r / (Cn * Cn);
    int rr = r % (Cn * Cn);
    int o = rr >> 9, i = rr & 511;
    const float* W = layer ? w1 : w0;
    float v = W[((size_t)o * Cn + i) * 9 + tap];
    __nv_bfloat16 h = __float2bfloat16(v);
    __nv_bfloat16 l = __float2bfloat16(v - __bfloat162float(h));
    size_t a = ((size_t)tap * Cn + o) * Cn + i;
    if (layer) { g_wt1H[a] = h; g_wt1L[a] = l; }
    else       { g_wt0H[a] = h; g_wt0L[a] = l; }
}

// ---------------------------------------------------------------------------
// zero the halo borders of the 4 activation planes (uint32 = 2 channels)
// ---------------------------------------------------------------------------
__global__ void k_zero()
{
    int idx = blockIdx.x * blockDim.x + threadIdx.x;
    if (idx >= Bn * 260 * 256) return;
    int c2 = idx & 255;
    int cell = (idx >> 8) % 260;
    int b = (idx >> 8) / 260;
    int y, x;
    if (cell < 66)       { y = 0;  x = cell; }
    else if (cell < 132) { y = 65; x = cell - 66; }
    else { int r = cell - 132; y = 1 + (r & 63); x = (r >> 6) ? 65 : 0; }
    size_t a = ((((size_t)b * PADHW + y) * PADHW + x) * Cn) / 2 + c2;
    ((uint32_t*)g_xaH)[a] = 0u;
    ((uint32_t*)g_xaL)[a] = 0u;
    ((uint32_t*)g_xbH)[a] = 0u;
    ((uint32_t*)g_xbL)[a] = 0u;
}

// ---------------------------------------------------------------------------
// upsample maps 2x bilinear, *s0, write padded HWC hi/lo planes
// ---------------------------------------------------------------------------
__global__ void __launch_bounds__(256) k_up(const float* __restrict__ maps)
{
    __shared__ uint32_t tile[64 * 65];
    int bx = blockIdx.x;
    int b = bx >> 6, y = bx & 63;
    int tid = threadIdx.x;

    int yl = (y - 1) >> 1, yu = yl + 1;
    float wyu = (y & 1) ? 0.25f : 0.75f;
    yl = max(yl, 0); yu = min(yu, HIN - 1);

    for (int c0 = 0; c0 < Cn; c0 += 64) {
        #pragma unroll
        for (int k = 0; k < 16; ++k) {
            int e = tid + (k << 8);
            int c = e >> 6, x = e & 63;
            int xl = (x - 1) >> 1, xu = xl + 1;
            float wxu = (x & 1) ? 0.25f : 0.75f;
            xl = max(xl, 0); xu = min(xu, HIN - 1);
            const float* p = maps + (size_t)(b * Cn + c0 + c) * (HIN * HIN);
            float v = (1.f - wyu) * ((1.f - wxu) * p[yl*HIN+xl] + wxu * p[yl*HIN+xu])
                    +         wyu * ((1.f - wxu) * p[yu*HIN+xl] + wxu * p[yu*HIN+xu]);
            v *= g_s0[b * Cn + c0 + c];
            __nv_bfloat16 h = __float2bfloat16(v);
            __nv_bfloat16 l = __float2bfloat16(v - __bfloat162float(h));
            tile[c * 65 + x] = ((uint32_t)__bfloat16_as_ushort(l) << 16) |
                               (uint32_t)__bfloat16_as_ushort(h);
        }
        __syncthreads();
        #pragma unroll
        for (int k = 0; k < 16; ++k) {
            int e = tid + (k << 8);
            int x = e >> 6, c = e & 63;
            uint32_t pk = tile[c * 65 + x];
            size_t a = (((size_t)b * PADHW + y + 1) * PADHW + x + 1) * Cn + c0 + c;
            g_xaH[a] = __ushort_as_bfloat16((unsigned short)(pk & 0xffff));
            g_xaL[a] = __ushort_as_bfloat16((unsigned short)(pk >> 16));
        }
        __syncthreads();
    }
}

// ---------------------------------------------------------------------------
// cp.async staging: one K-chunk (tap, 64 ic) -> smem AH/AL/BH/BL tiles
// (each 128 rows x 128B, XOR-swizzled). 512 threads x 8 x 16B = 64KB.
// ---------------------------------------------------------------------------
__device__ __forceinline__ void stage_cp(
    uint32_t sbase, int stg,
    const __nv_bfloat16* __restrict__ xH, const __nv_bfloat16* __restrict__ xL,
    const __nv_bfloat16* __restrict__ wH, const __nv_bfloat16* __restrict__ wL,
    int o0, int b, int y0, int chunk, int tid)
{
    const int tap = chunk >> 3;
    const int ic0 = (chunk & 7) << 6;
    const int ky = tap / 3;
    const int kx = tap - ky * 3;
    const uint32_t base = sbase + stg * 65536;
    #pragma unroll
    for (int k = 0; k < 8; ++k) {
        const int region = k >> 1;              // 0 AH, 1 AL, 2 BH, 3 BL
        const int s = tid + ((k & 1) << 9);     // 0..1023 within region
        const int r = s >> 3;                   // row 0..127
        const int g = s & 7;                    // 16B segment in row
        const __nv_bfloat16* src;
        if (region < 2) {
            const __nv_bfloat16* wp = region ? wL : wH;
            src = wp + ((size_t)tap * Cn + o0 + r) * Cn + ic0 + g * 8;
        } else {
            const __nv_bfloat16* xp = (region == 2) ? xH : xL;
            int dy = r >> 6, x = r & 63;
            src = xp + (((size_t)b * PADHW + y0 + dy + ky) * PADHW + x + kx) * Cn
                     + ic0 + g * 8;
        }
        uint32_t off = (uint32_t)((r << 7) + (g << 4));
        off ^= (off >> 3) & 0x70;
        cp16(base + region * 16384 + off, src);
    }
}

// ---------------------------------------------------------------------------
// conv via mma.sync: D[128 oc, 128 px] over 72 chunks, 3 MMAs per K=16 step.
// 512 threads, 16 warps in 4(m) x 4(n) grid, warp tile 32oc x 32px.
// EPI=0: -> hi/lo planes, padded HWC, pre-scaled by next style
// EPI=1: -> fp32 NCHW into d_out x region
// ---------------------------------------------------------------------------
template<int EPI>
__global__ void __launch_bounds__(512) k_conv(
    const __nv_bfloat16* __restrict__ xH, const __nv_bfloat16* __restrict__ xL,
    const __nv_bfloat16* __restrict__ wH, const __nv_bfloat16* __restrict__ wL,
    const float* __restrict__ dmod,
    const float* __restrict__ bias,
    const float* __restrict__ nsc,
    const float* __restrict__ noise,
    const float* __restrict__ post,
    __nv_bfloat16* __restrict__ outH, __nv_bfloat16* __restrict__ outL,
    float* __restrict__ outF)
{
    extern __shared__ __align__(16) char dsm_raw[];
    char* dbase = (char*)(((uintptr_t)dsm_raw + 1023) & ~(uintptr_t)1023);
    const uint32_t sb = smem_u32(dbase);
    const int tid = threadIdx.x;
    const int lane = tid & 31, wid = tid >> 5;
    const int mw = wid >> 2, nw = wid & 3;
    const int nt = blockIdx.x;
    const int o0 = blockIdx.y * 128;
    const int b  = nt >> 5;
    const int y0 = (nt & 31) * 2;

    float acc[2][4][4] = {};

    const int a_row = lane & 15;
    const int a_c16 = (lane >> 4) << 4;
    const int b_row = lane & 7;
    const int b_c16 = ((lane >> 3) & 1) << 4;

    stage_cp(sb, 0, xH, xL, wH, wL, o0, b, y0, 0, tid);
    CP_COMMIT();
    stage_cp(sb, 1, xH, xL, wH, wL, o0, b, y0, 1, tid);
    CP_COMMIT();

    int cur = 0, nxt = 2;
    for (int c = 0; c < 72; ++c) {
        CP_WAIT1();
        __syncthreads();
        if (c + 2 < 72)
            stage_cp(sb, nxt, xH, xL, wH, wL, o0, b, y0, c + 2, tid);
        CP_COMMIT();

        const uint32_t AHb = sb + cur * 65536;
        const uint32_t ALb = AHb + 16384;
        const uint32_t BHb = AHb + 32768;
        const uint32_t BLb = AHb + 49152;

        #pragma unroll
        for (int ks = 0; ks < 4; ++ks) {
            uint32_t ah[2][4], al[2][4], bh[4][2], bl[4][2];
            #pragma unroll
            for (int sm = 0; sm < 2; ++sm) {
                uint32_t off = (uint32_t)((mw * 32 + sm * 16 + a_row) * 128 + ks * 32 + a_c16);
                off ^= (off >> 3) & 0x70;
                ldsm_x4(ah[sm], AHb + off);
                ldsm_x4(al[sm], ALb + off);
            }
            #pragma unroll
            for (int sn = 0; sn < 4; ++sn) {
                uint32_t off = (uint32_t)((nw * 32 + sn * 8 + b_row) * 128 + ks * 32 + b_c16);
                off ^= (off >> 3) & 0x70;
                ldsm_x2(bh[sn], BHb + off);
                ldsm_x2(bl[sn], BLb + off);
            }
            #pragma unroll
            for (int sm = 0; sm < 2; ++sm)
                #pragma unroll
                for (int sn = 0; sn < 4; ++sn) {
                    mma_bf16(acc[sm][sn], ah[sm], bh[sn]);
                    mma_bf16(acc[sm][sn], ah[sm], bl[sn]);
                    mma_bf16(acc[sm][sn], al[sm], bh[sn]);
                }
        }
        cur = (cur == 2) ? 0 : cur + 1;
        nxt = (nxt == 2) ? 0 : nxt + 1;
    }

    // ---- epilogue. c-frag: e0,e1=(row, col,col+1) e2,e3=(row+8, ..)
    const int groupM = lane >> 2;
    const int groupN = 2 * (lane & 3);
    const float* np = noise + (size_t)b * PIX + y0 * 64;

    if (EPI == 0) {
        __syncthreads();                      // all MMA smem reads done
        uint32_t* tp = (uint32_t*)dbase;      // [128 px][132] (hi,lo) pairs
        #pragma unroll
        for (int sm = 0; sm < 2; ++sm) {
            #pragma unroll
            for (int ro = 0; ro < 2; ++ro) {
                int ocl = mw * 32 + sm * 16 + groupM + ro * 8;
                int oc = o0 + ocl;
                float d  = dmod[b * Cn + oc];
                float bi = bias[oc];
                float nv = nsc[oc];
                float ps = post[b * Cn + oc];
                #pragma unroll
                for (int sn = 0; sn < 4; ++sn) {
                    int px = nw * 32 + sn * 8 + groupN;
                    #pragma unroll
                    for (int e = 0; e < 2; ++e) {
                        float v = acc[sm][sn][ro * 2 + e] * d + bi + nv * np[px + e];
                        v = (v >= 0.f) ? v : 0.2f * v;
                        v *= ps;
                        __nv_bfloat16 h = __float2bfloat16(v);
                        __nv_bfloat16 l = __float2bfloat16(v - __bfloat162float(h));
                        tp[(px + e) * 132 + ocl] =
                            ((uint32_t)__bfloat16_as_ushort(l) << 16) |
                            (uint32_t)__bfloat16_as_ushort(h);
                    }
                }
            }
        }
        __syncthreads();
        int p = tid >> 2, q = tid & 3;
        int yy = y0 + (p >> 6), xx = p & 63;
        size_t abase = (((size_t)b * PADHW + yy + 1) * PADHW + xx + 1) * Cn + o0 + q * 32;
        uint4* dstH = (uint4*)(outH + abase);
        uint4* dstL = (uint4*)(outL + abase);
        const uint32_t* srcp = tp + p * 132 + q * 32;
        #pragma unroll
        for (int i = 0; i < 4; ++i) {
            uint32_t s0 = srcp[i*8+0], s1 = srcp[i*8+1], s2 = srcp[i*8+2], s3 = srcp[i*8+3];
            uint32_t s4 = srcp[i*8+4], s5 = srcp[i*8+5], s6 = srcp[i*8+6], s7 = srcp[i*8+7];
            dstH[i] = make_uint4(__byte_perm(s0,s1,0x5410), __byte_perm(s2,s3,0x5410),
                                 __byte_perm(s4,s5,0x5410), __byte_perm(s6,s7,0x5410));
            dstL[i] = make_uint4(__byte_perm(s0,s1,0x7632), __byte_perm(s2,s3,0x7632),
                                 __byte_perm(s4,s5,0x7632), __byte_perm(s6,s7,0x7632));
        }
    } else {
        #pragma unroll
        for (int sm = 0; sm < 2; ++sm) {
            #pragma unroll
            for (int ro = 0; ro < 2; ++ro) {
                int ocl = mw * 32 + sm * 16 + groupM + ro * 8;
                int oc = o0 + ocl;
                float d  = dmod[b * Cn + oc];
                float bi = bias[oc];
                float nv = nsc[oc];
                #pragma unroll
                for (int sn = 0; sn < 4; ++sn) {
                    int px = nw * 32 + sn * 8 + groupN;
                    float v0 = acc[sm][sn][ro * 2 + 0] * d + bi + nv * np[px + 0];
                    float v1 = acc[sm][sn][ro * 2 + 1] * d + bi + nv * np[px + 1];
                    v0 = (v0 >= 0.f) ? v0 : 0.2f * v0;
                    v1 = (v1 >= 0.f) ? v1 : 0.2f * v1;
                    int y = y0 + (px >> 6), x = px & 63;
                    float2* dp = (float2*)(outF + ((size_t)(b * Cn + oc) * 64 + y) * 64 + x);
                    *dp = make_float2(v0, v1);
                }
            }
        }
    }
}

// ---------------------------------------------------------------------------
// to_rgb: rgb_out = up2(rgb) + rgbB + (rgbW*s2) . x
// ---------------------------------------------------------------------------
__global__ void __launch_bounds__(256) k_rgb(
    const float* __restrict__ x,
    const float* __restrict__ rgb,
    const float* __restrict__ rgbW,
    const float* __restrict__ rgbB,
    float* __restrict__ outRGB)
{
    __shared__ float ws[3 * Cn];
    int b    = blockIdx.x >> 4;
    int yblk = blockIdx.x & 15;
    int tid  = threadIdx.x;

    for (int idx = tid; idx < 3 * Cn; idx += 256)
        ws[idx] = rgbW[idx] * g_s2[b * Cn + (idx & (Cn - 1))];
    __syncthreads();

    int dy = tid >> 6;
    int X  = tid & 63;
    int Y  = yblk * 4 + dy;

    const float* xp = x + (size_t)b * Cn * PIX + Y * 64 + X;
    float a0 = 0.f, a1 = 0.f, a2 = 0.f;
    #pragma unroll 8
    for (int c = 0; c < Cn; ++c) {
        float v = xp[(size_t)c * PIX];
        a0 += ws[c] * v;
        a1 += ws[Cn + c] * v;
        a2 += ws[2 * Cn + c] * v;
    }

    int yl = (Y - 1) >> 1; int yu = yl + 1;
    float wyu = (Y & 1) ? 0.25f : 0.75f;
    yl = max(yl, 0); yu = min(yu, HIN - 1);
    int xl = (X - 1) >> 1; int xu = xl + 1;
    float wxu = (X & 1) ? 0.25f : 0.75f;
    xl = max(xl, 0); xu = min(xu, HIN - 1);

    float accs[3] = {a0, a1, a2};
    #pragma unroll
    for (int r = 0; r < 3; ++r) {
        const float* p = rgb + (size_t)(b * 3 + r) * (HIN * HIN);
        float up = (1.f - wyu) * ((1.f - wxu) * p[yl*HIN+xl] + wxu * p[yl*HIN+xu])
                 +         wyu * ((1.f - wxu) * p[yu*HIN+xl] + wxu * p[yu*HIN+xu]);
        outRGB[((size_t)(b * 3 + r) * 64 + Y) * 64 + X] = up + accs[r] + rgbB[r];
    }
}

// ---------------------------------------------------------------------------
extern "C" void kernel_launch(void* const* d_in, const int* in_sizes, int n_in,
                              void* d_out, int out_size)
{
    const float* maps   = (const float*)d_in[0];
    const float* w      = (const float*)d_in[1];
    const float* rgb    = (const float*)d_in[2];
    const float* noise0 = (const float*)d_in[3];
    const float* noise1 = (const float*)d_in[4];
    const float* w0     = (const float*)d_in[5];
    const float* b0     = (const float*)d_in[6];
    const float* sW0    = (const float*)d_in[7];
    const float* sB0    = (const float*)d_in[8];
    const float* ns0    = (const float*)d_in[9];
    const float* w1     = (const float*)d_in[10];
    const float* b1     = (const float*)d_in[11];
    const float* sW1    = (const float*)d_in[12];
    const float* sB1    = (const float*)d_in[13];
    const float* ns1    = (const float*)d_in[14];
    const float* rgbW   = (const float*)d_in[15];
    const float* rgbB   = (const float*)d_in[16];
    const float* rgbSW  = (const float*)d_in[17];
    const float* rgbSB  = (const float*)d_in[18];

    float* out    = (float*)d_out;
    float* outRGB = out;
    float* outX   = out + RGBELEMS;

    __nv_bfloat16 *xaH, *xaL, *xbH, *xbL, *wt0H, *wt0L, *wt1H, *wt1L;
    float *d0p, *d1p, *s1p;
    cudaGetSymbolAddress((void**)&xaH, g_xaH);
    cudaGetSymbolAddress((void**)&xaL, g_xaL);
    cudaGetSymbolAddress((void**)&xbH, g_xbH);
    cudaGetSymbolAddress((void**)&xbL, g_xbL);
    cudaGetSymbolAddress((void**)&wt0H, g_wt0H);
    cudaGetSymbolAddress((void**)&wt0L, g_wt0L);
    cudaGetSymbolAddress((void**)&wt1H, g_wt1H);
    cudaGetSymbolAddress((void**)&wt1L, g_wt1L);
    cudaGetSymbolAddress((void**)&d0p, g_d0);
    cudaGetSymbolAddress((void**)&d1p, g_d1);
    cudaGetSymbolAddress((void**)&s1p, g_s1);

    const int DSM = 1024 + 3 * 65536;
    cudaFuncSetAttribute(k_conv<0>, cudaFuncAttributeMaxDynamicSharedMemorySize, DSM);
    cudaFuncSetAttribute(k_conv<1>, cudaFuncAttributeMaxDynamicSharedMemorySize, DSM);

    k_styles<<<(3 * Bn * Cn + 255) / 256, 256>>>(w, sW0, sB0, sW1, sB1, rgbSW, rgbSB);
    k_wsq<<<(2 * Cn * Cn + 255) / 256, 256>>>(w0, w1);
    k_demod<<<(2 * Bn * Cn + 255) / 256, 256>>>();
    k_wprep<<<(2 * 9 * Cn * Cn + 255) / 256, 256>>>(w0, w1);
    k_zero<<<(Bn * 260 * 256 + 255) / 256, 256>>>();
    k_up<<<Bn * 64, 256>>>(maps);

    dim3 gconv(256, 4);
    k_conv<0><<<gconv, 512, DSM>>>(xaH, xaL, wt0H, wt0L, d0p, b0, ns0, noise0,
                                   s1p, xbH, xbL, nullptr);
    k_conv<1><<<gconv, 512, DSM>>>(xbH, xbL, wt1H, wt1L, d1p, b1, ns1, noise1,
                                   nullptr, nullptr, nullptr, outX);

    k_rgb<<<Bn * 16, 256>>>(outX, rgb, rgbW, rgbB, outRGB);
}